// round 5
// baseline (speedup 1.0000x reference)
#include <cuda_runtime.h>
#include <cuda_bf16.h>
#include <math.h>

#define NN 50000
#define NE 800000
#define IN_DIM 128
#define HID_DIM 256
#define OUT_DIM 64

// ---------------- device scratch (no allocations allowed) ----------------
__device__ int   g_is64;
__device__ int   g_src[NE];
__device__ int   g_dst[NE];
__device__ int   g_deg[NN];
__device__ int   g_off[NN + 1];
__device__ int   g_cursor[NN];
__device__ int   g_csr_src[NE];
__device__ float g_mean[(size_t)NN * IN_DIM];
__device__ float g_h[(size_t)NN * HID_DIM];

// ---------------- dtype probe: int64 (high words all 0) vs int32 ----------------
__global__ void detect_kernel(const unsigned int* __restrict__ ei32) {
    __shared__ int nz;
    if (threadIdx.x == 0) nz = 0;
    __syncthreads();
    int cnt = 0;
    for (int i = threadIdx.x; i < 4096; i += blockDim.x)
        if (ei32[2 * i + 1] != 0u) cnt++;
    atomicAdd(&nz, cnt);
    __syncthreads();
    if (threadIdx.x == 0) g_is64 = (nz == 0) ? 1 : 0;
}

__global__ void zero_deg_kernel() {
    int i = blockIdx.x * blockDim.x + threadIdx.x;
    if (i < NN) g_deg[i] = 0;
}

// normalize edge_index to int arrays (clamped) + fused degree histogram
__global__ void convert_kernel(const void* __restrict__ ei) {
    int e = blockIdx.x * blockDim.x + threadIdx.x;
    if (e >= NE) return;
    int s, d;
    if (g_is64) {
        const long long* p = (const long long*)ei;
        s = (int)p[e];
        d = (int)p[NE + e];
    } else {
        const int* p = (const int*)ei;
        s = p[e];
        d = p[NE + e];
    }
    s = min(max(s, 0), NN - 1);
    d = min(max(d, 0), NN - 1);
    g_src[e] = s;
    g_dst[e] = d;
    atomicAdd(&g_deg[d], 1);
}

// single-block exclusive scan of g_deg -> g_off / g_cursor
__global__ void scan_kernel() {
    __shared__ int sm[1024];
    __shared__ int carry_s;
    int t = threadIdx.x;
    if (t == 0) carry_s = 0;
    __syncthreads();
    for (int base = 0; base < NN; base += 1024) {
        int v = (base + t < NN) ? g_deg[base + t] : 0;
        sm[t] = v;
        __syncthreads();
        #pragma unroll
        for (int off = 1; off < 1024; off <<= 1) {
            int u = 0;
            if (t >= off) u = sm[t - off];
            __syncthreads();
            sm[t] += u;
            __syncthreads();
        }
        int incl = sm[t];
        int carry = carry_s;
        int excl = incl - v + carry;
        if (base + t < NN) {
            g_off[base + t]    = excl;
            g_cursor[base + t] = excl;
        }
        __syncthreads();
        if (t == 0) carry_s = carry + sm[1023];
        __syncthreads();
    }
    if (t == 0) g_off[NN] = carry_s;
}

__global__ void scatter_kernel() {
    int e = blockIdx.x * blockDim.x + threadIdx.x;
    if (e < NE) {
        int d = g_dst[e];
        int s = g_src[e];
        int pos = atomicAdd(&g_cursor[d], 1);
        g_csr_src[pos] = s;
    }
}

// ---------------- mean aggregation (atomic-free, 1 node / 128-thread block) ----------------
__global__ void __launch_bounds__(128) agg_kernel(const float* __restrict__ x) {
    int node = blockIdx.x;
    int t = threadIdx.x;
    int beg = g_off[node];
    int end = g_off[node + 1];
    float acc = 0.f;
    for (int e = beg; e < end; e++) {
        int s = g_csr_src[e];
        acc += __ldg(&x[(size_t)s * IN_DIM + t]);
    }
    int d = end - beg;
    float inv = (d > 0) ? 1.0f / (float)d : 0.f;  // deg=0 -> mean 0 (matches ref)
    g_mean[(size_t)node * IN_DIM + t] = acc * inv;
}

// ---------------- GEMM1: H = elu([mean|x] @ [W_l;W_r] + b_l) ----------------
// BM=128, BN=128, BK=16, virtual K=256. 256 threads, 8x8 microtile.
__global__ void __launch_bounds__(256) gemm1_kernel(const float* __restrict__ x,
                                                    const float* __restrict__ Wl,
                                                    const float* __restrict__ Wr,
                                                    const float* __restrict__ bl) {
    __shared__ float As[16][128];
    __shared__ float Bs[16][128];
    const int tid = threadIdx.x;
    const int rowBase = blockIdx.x * 128;
    const int colBase = blockIdx.y * 128;
    const int tr = tid / 16;   // 0..15
    const int tc = tid % 16;   // 0..15

    float acc[8][8];
    #pragma unroll
    for (int i = 0; i < 8; i++)
        #pragma unroll
        for (int j = 0; j < 8; j++) acc[i][j] = 0.f;

    for (int kt = 0; kt < 16; kt++) {
        const bool first = (kt < 8);
        const float* Asrc = first ? (const float*)g_mean : x;
        const float* Bsrc = first ? Wl : Wr;
        const int kb = (first ? kt : kt - 8) * 16;

        // load A tile (128x16) transposed into As[k][m]; 2 float4 per thread
        #pragma unroll
        for (int r = 0; r < 2; r++) {
            int idx = tid + r * 256;          // 0..511
            int row = idx >> 2;               // 0..127
            int c4  = idx & 3;                // 0..3
            int grow = rowBase + row;
            float4 v = make_float4(0.f, 0.f, 0.f, 0.f);
            if (grow < NN)
                v = *(const float4*)&Asrc[(size_t)grow * IN_DIM + kb + c4 * 4];
            As[c4 * 4 + 0][row] = v.x;
            As[c4 * 4 + 1][row] = v.y;
            As[c4 * 4 + 2][row] = v.z;
            As[c4 * 4 + 3][row] = v.w;
        }
        // load B tile (16x128); 2 float4 per thread
        #pragma unroll
        for (int r = 0; r < 2; r++) {
            int idx = tid + r * 256;          // 0..511
            int k  = idx >> 5;                // 0..15
            int c4 = idx & 31;                // 0..31
            float4 v = *(const float4*)&Bsrc[(size_t)(kb + k) * HID_DIM + colBase + c4 * 4];
            *(float4*)&Bs[k][c4 * 4] = v;
        }
        __syncthreads();

        #pragma unroll
        for (int k = 0; k < 16; k++) {
            float a[8], b[8];
            #pragma unroll
            for (int i = 0; i < 8; i++) a[i] = As[k][tr * 8 + i];
            #pragma unroll
            for (int j = 0; j < 8; j++) b[j] = Bs[k][tc * 8 + j];
            #pragma unroll
            for (int i = 0; i < 8; i++)
                #pragma unroll
                for (int j = 0; j < 8; j++) acc[i][j] += a[i] * b[j];
        }
        __syncthreads();
    }

    // epilogue: +b_l, ELU, store to g_h
    #pragma unroll
    for (int i = 0; i < 8; i++) {
        int grow = rowBase + tr * 8 + i;
        if (grow >= NN) continue;
        #pragma unroll
        for (int j = 0; j < 8; j++) {
            int col = colBase + tc * 8 + j;
            float v = acc[i][j] + bl[col];
            v = (v > 0.f) ? v : expm1f(v);
            g_h[(size_t)grow * HID_DIM + col] = v;
        }
    }
}

// ---------------- GEMM2: out = H @ W_out + b_out ----------------
// BM=128, BN=64, BK=16, K=256. 128 threads, 8x8 microtile.
__global__ void __launch_bounds__(128) gemm2_kernel(const float* __restrict__ Wout,
                                                    const float* __restrict__ bout,
                                                    float* __restrict__ out) {
    __shared__ float As[16][128];
    __shared__ float Bs[16][64];
    const int tid = threadIdx.x;
    const int rowBase = blockIdx.x * 128;
    const int tr = tid / 8;   // 0..15
    const int tc = tid % 8;   // 0..7

    float acc[8][8];
    #pragma unroll
    for (int i = 0; i < 8; i++)
        #pragma unroll
        for (int j = 0; j < 8; j++) acc[i][j] = 0.f;

    for (int kt = 0; kt < 16; kt++) {
        const int kb = kt * 16;
        // A tile 128x16 -> 512 float4, 4 per thread
        #pragma unroll
        for (int r = 0; r < 4; r++) {
            int idx = tid + r * 128;
            int row = idx >> 2;
            int c4  = idx & 3;
            int grow = rowBase + row;
            float4 v = make_float4(0.f, 0.f, 0.f, 0.f);
            if (grow < NN)
                v = *(const float4*)&g_h[(size_t)grow * HID_DIM + kb + c4 * 4];
            As[c4 * 4 + 0][row] = v.x;
            As[c4 * 4 + 1][row] = v.y;
            As[c4 * 4 + 2][row] = v.z;
            As[c4 * 4 + 3][row] = v.w;
        }
        // B tile 16x64 -> 256 float4, 2 per thread
        #pragma unroll
        for (int r = 0; r < 2; r++) {
            int idx = tid + r * 128;          // 0..255
            int k  = idx >> 4;                // 0..15
            int c4 = idx & 15;                // 0..15
            float4 v = *(const float4*)&Wout[(size_t)(kb + k) * OUT_DIM + c4 * 4];
            *(float4*)&Bs[k][c4 * 4] = v;
        }
        __syncthreads();

        #pragma unroll
        for (int k = 0; k < 16; k++) {
            float a[8], b[8];
            #pragma unroll
            for (int i = 0; i < 8; i++) a[i] = As[k][tr * 8 + i];
            #pragma unroll
            for (int j = 0; j < 8; j++) b[j] = Bs[k][tc * 8 + j];
            #pragma unroll
            for (int i = 0; i < 8; i++)
                #pragma unroll
                for (int j = 0; j < 8; j++) acc[i][j] += a[i] * b[j];
        }
        __syncthreads();
    }

    #pragma unroll
    for (int i = 0; i < 8; i++) {
        int grow = rowBase + tr * 8 + i;
        if (grow >= NN) continue;
        #pragma unroll
        for (int j = 0; j < 8; j++) {
            int col = tc * 8 + j;
            out[(size_t)grow * OUT_DIM + col] = acc[i][j] + bout[col];
        }
    }
}

// ---------------- launch ----------------
extern "C" void kernel_launch(void* const* d_in, const int* in_sizes, int n_in,
                              void* d_out, int out_size) {
    const float* x    = (const float*)d_in[0];
    const void*  ei   = d_in[1];
    const float* Wl   = (const float*)d_in[2];
    const float* bl   = (const float*)d_in[3];
    const float* Wr   = (const float*)d_in[4];
    const float* Wout = (const float*)d_in[5];
    const float* bout = (const float*)d_in[6];
    float* out = (float*)d_out;

    detect_kernel<<<1, 256>>>((const unsigned int*)ei);
    zero_deg_kernel<<<(NN + 255) / 256, 256>>>();
    convert_kernel<<<(NE + 255) / 256, 256>>>(ei);
    scan_kernel<<<1, 1024>>>();
    scatter_kernel<<<(NE + 255) / 256, 256>>>();
    agg_kernel<<<NN, 128>>>(x);

    dim3 g1((NN + 127) / 128, HID_DIM / 128);
    gemm1_kernel<<<g1, 256>>>(x, Wl, Wr, bl);

    gemm2_kernel<<<(NN + 127) / 128, 128>>>(Wout, bout, out);
}

// round 7
// speedup vs baseline: 1.2222x; 1.2222x over previous
#include <cuda_runtime.h>
#include <cuda_bf16.h>
#include <math.h>

#define NN 50000
#define NE 800000
#define IN_DIM 128
#define HID_DIM 256
#define OUT_DIM 64
#define SCAN_BLOCKS ((NN + 1023) / 1024)   // 49

// ---------------- device scratch (no allocations allowed) ----------------
__device__ int   g_is64;
__device__ int   g_src[NE];
__device__ int   g_dst[NE];
__device__ int   g_deg[NN];
__device__ int   g_off[NN + 1];
__device__ int   g_cursor[NN];
__device__ int   g_csr_src[NE];
__device__ int   g_tilesum[SCAN_BLOCKS];
__device__ int   g_tileoff[SCAN_BLOCKS];
__device__ float g_mean[(size_t)NN * IN_DIM];
__device__ float g_h[(size_t)NN * HID_DIM];

// ---------------- dtype probe: int64 (high words all 0) vs int32 ----------------
__global__ void detect_kernel(const unsigned int* __restrict__ ei32) {
    __shared__ int nz;
    if (threadIdx.x == 0) nz = 0;
    __syncthreads();
    int cnt = 0;
    for (int i = threadIdx.x; i < 4096; i += blockDim.x)
        if (ei32[2 * i + 1] != 0u) cnt++;
    atomicAdd(&nz, cnt);
    __syncthreads();
    if (threadIdx.x == 0) g_is64 = (nz == 0) ? 1 : 0;
}

__global__ void zero_deg_kernel() {
    int i = blockIdx.x * blockDim.x + threadIdx.x;
    if (i < NN) g_deg[i] = 0;
}

// normalize edge_index to int arrays (clamped) + fused degree histogram
__global__ void convert_kernel(const void* __restrict__ ei) {
    int e = blockIdx.x * blockDim.x + threadIdx.x;
    if (e >= NE) return;
    int s, d;
    if (g_is64) {
        const long long* p = (const long long*)ei;
        s = (int)p[e];
        d = (int)p[NE + e];
    } else {
        const int* p = (const int*)ei;
        s = p[e];
        d = p[NE + e];
    }
    s = min(max(s, 0), NN - 1);
    d = min(max(d, 0), NN - 1);
    g_src[e] = s;
    g_dst[e] = d;
    atomicAdd(&g_deg[d], 1);
}

// ---------------- fast 3-phase scan ----------------
// phase 1: per-block (1024 elems) exclusive scan via warp shuffles; emit tile sums
__global__ void __launch_bounds__(1024) scan1_kernel() {
    __shared__ int wsum[32];
    int b = blockIdx.x, t = threadIdx.x;
    int i = b * 1024 + t;
    int v = (i < NN) ? g_deg[i] : 0;
    int lane = t & 31, w = t >> 5;
    int x = v;
    #pragma unroll
    for (int o = 1; o < 32; o <<= 1) {
        int y = __shfl_up_sync(0xFFFFFFFFu, x, o);
        if (lane >= o) x += y;
    }
    if (lane == 31) wsum[w] = x;
    __syncthreads();
    if (w == 0) {
        int s = wsum[lane];
        #pragma unroll
        for (int o = 1; o < 32; o <<= 1) {
            int y = __shfl_up_sync(0xFFFFFFFFu, s, o);
            if (lane >= o) s += y;
        }
        wsum[lane] = s;
    }
    __syncthreads();
    int incl = x + (w > 0 ? wsum[w - 1] : 0);
    if (i < NN) g_off[i] = incl - v;          // local exclusive
    if (t == 1023) g_tilesum[b] = incl;       // tile total
}

// phase 2: one warp scans the 49 tile sums
__global__ void scan2_kernel() {
    int lane = threadIdx.x;                                   // 32 threads
    int v0 = (lane < SCAN_BLOCKS) ? g_tilesum[lane] : 0;
    int v1 = (32 + lane < SCAN_BLOCKS) ? g_tilesum[32 + lane] : 0;
    int s0 = v0;
    #pragma unroll
    for (int o = 1; o < 32; o <<= 1) {
        int y = __shfl_up_sync(0xFFFFFFFFu, s0, o);
        if (lane >= o) s0 += y;
    }
    int tot0 = __shfl_sync(0xFFFFFFFFu, s0, 31);
    int s1 = v1;
    #pragma unroll
    for (int o = 1; o < 32; o <<= 1) {
        int y = __shfl_up_sync(0xFFFFFFFFu, s1, o);
        if (lane >= o) s1 += y;
    }
    s1 += tot0;
    if (lane < SCAN_BLOCKS) g_tileoff[lane] = s0 - v0;
    if (32 + lane < SCAN_BLOCKS) g_tileoff[32 + lane] = s1 - v1;
    int total = __shfl_sync(0xFFFFFFFFu, s1, SCAN_BLOCKS - 32 - 1);
    if (lane == 0) g_off[NN] = total;
}

// phase 3: add tile offsets, fill cursor
__global__ void __launch_bounds__(1024) scan3_kernel() {
    int i = blockIdx.x * 1024 + threadIdx.x;
    if (i < NN) {
        int o = g_off[i] + g_tileoff[i >> 10];
        g_off[i] = o;
        g_cursor[i] = o;
    }
}

__global__ void scatter_kernel() {
    int e = blockIdx.x * blockDim.x + threadIdx.x;
    if (e < NE) {
        int d = g_dst[e];
        int s = g_src[e];
        int pos = atomicAdd(&g_cursor[d], 1);
        g_csr_src[pos] = s;
    }
}

// ---------------- mean aggregation (atomic-free, 1 node / 128-thread block) ----------------
__global__ void __launch_bounds__(128) agg_kernel(const float* __restrict__ x) {
    int node = blockIdx.x;
    int t = threadIdx.x;
    int beg = g_off[node];
    int end = g_off[node + 1];
    float acc = 0.f;
    for (int e = beg; e < end; e++) {
        int s = g_csr_src[e];
        acc += __ldg(&x[(size_t)s * IN_DIM + t]);
    }
    int d = end - beg;
    float inv = (d > 0) ? 1.0f / (float)d : 0.f;  // deg=0 -> mean 0 (matches ref)
    g_mean[(size_t)node * IN_DIM + t] = acc * inv;
}

// ---------------- GEMM1: H = elu([mean|x] @ [W_l;W_r] + b_l) ----------------
// BM=128, BN=128, BK=16, virtual K=256. 256 threads, 8x8 microtile.
// Double-buffered: LDG for tile kt+1 overlaps FFMA on tile kt.
__global__ void __launch_bounds__(256) gemm1_kernel(const float* __restrict__ x,
                                                    const float* __restrict__ Wl,
                                                    const float* __restrict__ Wr,
                                                    const float* __restrict__ bl) {
    __shared__ float As[2][16][128];
    __shared__ float Bs[2][16][128];
    const int tid = threadIdx.x;
    const int rowBase = blockIdx.x * 128;
    const int colBase = blockIdx.y * 128;
    const int tr = tid / 16;   // 0..15
    const int tc = tid % 16;   // 0..15

    float acc[8][8];
    #pragma unroll
    for (int i = 0; i < 8; i++)
        #pragma unroll
        for (int j = 0; j < 8; j++) acc[i][j] = 0.f;

    float4 ra[2], rb[2];

    auto fetch = [&](int kt) {
        const bool first = (kt < 8);
        const float* Asrc = first ? (const float*)g_mean : x;
        const float* Bsrc = first ? Wl : Wr;
        const int kb = (first ? kt : kt - 8) * 16;
        #pragma unroll
        for (int r = 0; r < 2; r++) {
            int idx = tid + r * 256;          // 0..511
            int row = idx >> 2;               // 0..127
            int c4  = idx & 3;                // 0..3
            int grow = rowBase + row;
            float4 v = make_float4(0.f, 0.f, 0.f, 0.f);
            if (grow < NN)
                v = *(const float4*)&Asrc[(size_t)grow * IN_DIM + kb + c4 * 4];
            ra[r] = v;
        }
        #pragma unroll
        for (int r = 0; r < 2; r++) {
            int idx = tid + r * 256;          // 0..511
            int k  = idx >> 5;                // 0..15
            int c4 = idx & 31;                // 0..31
            rb[r] = *(const float4*)&Bsrc[(size_t)(kb + k) * HID_DIM + colBase + c4 * 4];
        }
    };
    auto stage = [&](int buf) {
        #pragma unroll
        for (int r = 0; r < 2; r++) {
            int idx = tid + r * 256;
            int row = idx >> 2;
            int c4  = idx & 3;
            As[buf][c4 * 4 + 0][row] = ra[r].x;
            As[buf][c4 * 4 + 1][row] = ra[r].y;
            As[buf][c4 * 4 + 2][row] = ra[r].z;
            As[buf][c4 * 4 + 3][row] = ra[r].w;
        }
        #pragma unroll
        for (int r = 0; r < 2; r++) {
            int idx = tid + r * 256;
            int k  = idx >> 5;
            int c4 = idx & 31;
            *(float4*)&Bs[buf][k][c4 * 4] = rb[r];
        }
    };

    fetch(0);
    stage(0);
    __syncthreads();

    for (int kt = 0; kt < 16; kt++) {
        const int cur = kt & 1;
        if (kt < 15) fetch(kt + 1);          // LDGs in flight during compute

        #pragma unroll
        for (int k = 0; k < 16; k++) {
            float a[8], b[8];
            *(float4*)&a[0] = *(const float4*)&As[cur][k][tr * 8 + 0];
            *(float4*)&a[4] = *(const float4*)&As[cur][k][tr * 8 + 4];
            *(float4*)&b[0] = *(const float4*)&Bs[cur][k][tc * 8 + 0];
            *(float4*)&b[4] = *(const float4*)&Bs[cur][k][tc * 8 + 4];
            #pragma unroll
            for (int i = 0; i < 8; i++)
                #pragma unroll
                for (int j = 0; j < 8; j++) acc[i][j] += a[i] * b[j];
        }

        if (kt < 15) stage(cur ^ 1);
        __syncthreads();
    }

    // epilogue: +b_l, ELU, store to g_h
    #pragma unroll
    for (int i = 0; i < 8; i++) {
        int grow = rowBase + tr * 8 + i;
        if (grow >= NN) continue;
        #pragma unroll
        for (int j = 0; j < 8; j++) {
            int col = colBase + tc * 8 + j;
            float v = acc[i][j] + bl[col];
            v = (v > 0.f) ? v : expm1f(v);
            g_h[(size_t)grow * HID_DIM + col] = v;
        }
    }
}

// ---------------- GEMM2: out = H @ W_out + b_out ----------------
// BM=128, BN=64, BK=16, K=256. 128 threads, 8x8 microtile, double-buffered.
__global__ void __launch_bounds__(128) gemm2_kernel(const float* __restrict__ Wout,
                                                    const float* __restrict__ bout,
                                                    float* __restrict__ out) {
    __shared__ float As[2][16][128];
    __shared__ float Bs[2][16][64];
    const int tid = threadIdx.x;
    const int rowBase = blockIdx.x * 128;
    const int tr = tid / 8;   // 0..15
    const int tc = tid % 8;   // 0..7

    float acc[8][8];
    #pragma unroll
    for (int i = 0; i < 8; i++)
        #pragma unroll
        for (int j = 0; j < 8; j++) acc[i][j] = 0.f;

    float4 ra[4], rb[2];
    auto fetch = [&](int kt) {
        const int kb = kt * 16;
        #pragma unroll
        for (int r = 0; r < 4; r++) {
            int idx = tid + r * 128;
            int row = idx >> 2;
            int c4  = idx & 3;
            int grow = rowBase + row;
            float4 v = make_float4(0.f, 0.f, 0.f, 0.f);
            if (grow < NN)
                v = *(const float4*)&g_h[(size_t)grow * HID_DIM + kb + c4 * 4];
            ra[r] = v;
        }
        #pragma unroll
        for (int r = 0; r < 2; r++) {
            int idx = tid + r * 128;          // 0..255
            int k  = idx >> 4;                // 0..15
            int c4 = idx & 15;                // 0..15
            rb[r] = *(const float4*)&Wout[(size_t)(kb + k) * OUT_DIM + c4 * 4];
        }
    };
    auto stage = [&](int buf) {
        #pragma unroll
        for (int r = 0; r < 4; r++) {
            int idx = tid + r * 128;
            int row = idx >> 2;
            int c4  = idx & 3;
            As[buf][c4 * 4 + 0][row] = ra[r].x;
            As[buf][c4 * 4 + 1][row] = ra[r].y;
            As[buf][c4 * 4 + 2][row] = ra[r].z;
            As[buf][c4 * 4 + 3][row] = ra[r].w;
        }
        #pragma unroll
        for (int r = 0; r < 2; r++) {
            int idx = tid + r * 128;
            int k  = idx >> 4;
            int c4 = idx & 15;
            *(float4*)&Bs[buf][k][c4 * 4] = rb[r];
        }
    };

    fetch(0);
    stage(0);
    __syncthreads();

    for (int kt = 0; kt < 16; kt++) {
        const int cur = kt & 1;
        if (kt < 15) fetch(kt + 1);

        #pragma unroll
        for (int k = 0; k < 16; k++) {
            float a[8], b[8];
            *(float4*)&a[0] = *(const float4*)&As[cur][k][tr * 8 + 0];
            *(float4*)&a[4] = *(const float4*)&As[cur][k][tr * 8 + 4];
            *(float4*)&b[0] = *(const float4*)&Bs[cur][k][tc * 8 + 0];
            *(float4*)&b[4] = *(const float4*)&Bs[cur][k][tc * 8 + 4];
            #pragma unroll
            for (int i = 0; i < 8; i++)
                #pragma unroll
                for (int j = 0; j < 8; j++) acc[i][j] += a[i] * b[j];
        }

        if (kt < 15) stage(cur ^ 1);
        __syncthreads();
    }

    #pragma unroll
    for (int i = 0; i < 8; i++) {
        int grow = rowBase + tr * 8 + i;
        if (grow >= NN) continue;
        #pragma unroll
        for (int j = 0; j < 8; j++) {
            int col = tc * 8 + j;
            out[(size_t)grow * OUT_DIM + col] = acc[i][j] + bout[col];
        }
    }
}

// ---------------- launch ----------------
extern "C" void kernel_launch(void* const* d_in, const int* in_sizes, int n_in,
                              void* d_out, int out_size) {
    const float* x    = (const float*)d_in[0];
    const void*  ei   = d_in[1];
    const float* Wl   = (const float*)d_in[2];
    const float* bl   = (const float*)d_in[3];
    const float* Wr   = (const float*)d_in[4];
    const float* Wout = (const float*)d_in[5];
    const float* bout = (const float*)d_in[6];
    float* out = (float*)d_out;

    detect_kernel<<<1, 256>>>((const unsigned int*)ei);
    zero_deg_kernel<<<(NN + 255) / 256, 256>>>();
    convert_kernel<<<(NE + 255) / 256, 256>>>(ei);
    scan1_kernel<<<SCAN_BLOCKS, 1024>>>();
    scan2_kernel<<<1, 32>>>();
    scan3_kernel<<<SCAN_BLOCKS, 1024>>>();
    scatter_kernel<<<(NE + 255) / 256, 256>>>();
    agg_kernel<<<NN, 128>>>(x);

    dim3 g1((NN + 127) / 128, HID_DIM / 128);
    gemm1_kernel<<<g1, 256>>>(x, Wl, Wr, bl);

    gemm2_kernel<<<(NN + 127) / 128, 128>>>(Wout, bout, out);
}

// round 12
// speedup vs baseline: 1.8753x; 1.5343x over previous
#include <cuda_runtime.h>
#include <cuda_bf16.h>
#include <math.h>
#include <stdint.h>

#define NN 50000
#define NE 800000
#define IN_DIM 128
#define HID_DIM 256
#define OUT_DIM 64
#define SCAN_BLOCKS ((NN + 1023) / 1024)   // 49
#define MTILES ((NN + 127) / 128)          // 391

// ---------------- device scratch (no allocations allowed) ----------------
__device__ int   g_is64;
__device__ int   g_src[NE];
__device__ int   g_dst[NE];
__device__ int   g_deg[NN];
__device__ int   g_off[NN + 1];
__device__ int   g_cursor[NN];
__device__ int   g_csr_src[NE];
__device__ int   g_tilesum[SCAN_BLOCKS];
__device__ int   g_tileoff[SCAN_BLOCKS];
__device__ float g_mean[(size_t)NN * IN_DIM];
// split weight images, plain row-major [n][k] bf16
__device__ __align__(16) __nv_bfloat16 g_B1hi[HID_DIM * 256];   // [n=256][k=256]
__device__ __align__(16) __nv_bfloat16 g_B1lo[HID_DIM * 256];
__device__ __align__(16) __nv_bfloat16 g_B2hi[OUT_DIM * 256];   // [n=64][k=256]
__device__ __align__(16) __nv_bfloat16 g_B2lo[OUT_DIM * 256];
// hidden activations, bf16 split
__device__ __align__(16) __nv_bfloat16 g_hhi[(size_t)NN * HID_DIM];
__device__ __align__(16) __nv_bfloat16 g_hlo[(size_t)NN * HID_DIM];

// ---------------- helpers ----------------
__device__ __forceinline__ uint32_t s2u(const void* p) {
    uint32_t a;
    asm("{ .reg .u64 t; cvta.to.shared.u64 t, %1; cvt.u32.u64 %0, t; }" : "=r"(a) : "l"(p));
    return a;
}
__device__ __forceinline__ void ldsm4(uint32_t* r, uint32_t addr) {
    asm volatile("ldmatrix.sync.aligned.m8n8.x4.shared.b16 {%0,%1,%2,%3}, [%4];"
        : "=r"(r[0]), "=r"(r[1]), "=r"(r[2]), "=r"(r[3]) : "r"(addr));
}
__device__ __forceinline__ void mma16816(float* d, const uint32_t* a, uint32_t b0, uint32_t b1) {
    asm volatile("mma.sync.aligned.m16n8k16.row.col.f32.bf16.bf16.f32 "
        "{%0,%1,%2,%3}, {%4,%5,%6,%7}, {%8,%9}, {%0,%1,%2,%3};"
        : "+f"(d[0]), "+f"(d[1]), "+f"(d[2]), "+f"(d[3])
        : "r"(a[0]), "r"(a[1]), "r"(a[2]), "r"(a[3]), "r"(b0), "r"(b1));
}
__device__ __forceinline__ uint32_t pack2(__nv_bfloat16 a, __nv_bfloat16 b) {
    union { __nv_bfloat16 h[2]; uint32_t u; } t;
    t.h[0] = a; t.h[1] = b;
    return t.u;
}

// ---------------- dtype probe: int64 (high words all 0) vs int32 ----------------
__global__ void detect_kernel(const unsigned int* __restrict__ ei32) {
    __shared__ int nz;
    if (threadIdx.x == 0) nz = 0;
    __syncthreads();
    int cnt = 0;
    for (int i = threadIdx.x; i < 4096; i += blockDim.x)
        if (ei32[2 * i + 1] != 0u) cnt++;
    atomicAdd(&nz, cnt);
    __syncthreads();
    if (threadIdx.x == 0) g_is64 = (nz == 0) ? 1 : 0;
}

__global__ void zero_deg_kernel() {
    int i = blockIdx.x * blockDim.x + threadIdx.x;
    if (i < NN) g_deg[i] = 0;
}

__global__ void convert_kernel(const void* __restrict__ ei) {
    int e = blockIdx.x * blockDim.x + threadIdx.x;
    if (e >= NE) return;
    int s, d;
    if (g_is64) {
        const long long* p = (const long long*)ei;
        s = (int)p[e];
        d = (int)p[NE + e];
    } else {
        const int* p = (const int*)ei;
        s = p[e];
        d = p[NE + e];
    }
    s = min(max(s, 0), NN - 1);
    d = min(max(d, 0), NN - 1);
    g_src[e] = s;
    g_dst[e] = d;
    atomicAdd(&g_deg[d], 1);
}

// ---------------- fast 3-phase scan ----------------
__global__ void __launch_bounds__(1024) scan1_kernel() {
    __shared__ int wsum[32];
    int b = blockIdx.x, t = threadIdx.x;
    int i = b * 1024 + t;
    int v = (i < NN) ? g_deg[i] : 0;
    int lane = t & 31, w = t >> 5;
    int x = v;
    #pragma unroll
    for (int o = 1; o < 32; o <<= 1) {
        int y = __shfl_up_sync(0xFFFFFFFFu, x, o);
        if (lane >= o) x += y;
    }
    if (lane == 31) wsum[w] = x;
    __syncthreads();
    if (w == 0) {
        int s = wsum[lane];
        #pragma unroll
        for (int o = 1; o < 32; o <<= 1) {
            int y = __shfl_up_sync(0xFFFFFFFFu, s, o);
            if (lane >= o) s += y;
        }
        wsum[lane] = s;
    }
    __syncthreads();
    int incl = x + (w > 0 ? wsum[w - 1] : 0);
    if (i < NN) g_off[i] = incl - v;
    if (t == 1023) g_tilesum[b] = incl;
}

__global__ void scan2_kernel() {
    int lane = threadIdx.x;
    int v0 = (lane < SCAN_BLOCKS) ? g_tilesum[lane] : 0;
    int v1 = (32 + lane < SCAN_BLOCKS) ? g_tilesum[32 + lane] : 0;
    int s0 = v0;
    #pragma unroll
    for (int o = 1; o < 32; o <<= 1) {
        int y = __shfl_up_sync(0xFFFFFFFFu, s0, o);
        if (lane >= o) s0 += y;
    }
    int tot0 = __shfl_sync(0xFFFFFFFFu, s0, 31);
    int s1 = v1;
    #pragma unroll
    for (int o = 1; o < 32; o <<= 1) {
        int y = __shfl_up_sync(0xFFFFFFFFu, s1, o);
        if (lane >= o) s1 += y;
    }
    s1 += tot0;
    if (lane < SCAN_BLOCKS) g_tileoff[lane] = s0 - v0;
    if (32 + lane < SCAN_BLOCKS) g_tileoff[32 + lane] = s1 - v1;
    int total = __shfl_sync(0xFFFFFFFFu, s1, SCAN_BLOCKS - 32 - 1);
    if (lane == 0) g_off[NN] = total;
}

__global__ void __launch_bounds__(1024) scan3_kernel() {
    int i = blockIdx.x * 1024 + threadIdx.x;
    if (i < NN) {
        int o = g_off[i] + g_tileoff[i >> 10];
        g_off[i] = o;
        g_cursor[i] = o;
    }
}

__global__ void scatter_kernel() {
    int e = blockIdx.x * blockDim.x + threadIdx.x;
    if (e < NE) {
        int d = g_dst[e];
        int s = g_src[e];
        int pos = atomicAdd(&g_cursor[d], 1);
        g_csr_src[pos] = s;
    }
}

// ---------------- mean aggregation (atomic-free, 1 node / 128-thread block) ----------------
__global__ void __launch_bounds__(128) agg_kernel(const float* __restrict__ x) {
    int node = blockIdx.x;
    int t = threadIdx.x;
    int beg = g_off[node];
    int end = g_off[node + 1];
    float acc = 0.f;
    for (int e = beg; e < end; e++) {
        int s = g_csr_src[e];
        acc += __ldg(&x[(size_t)s * IN_DIM + t]);
    }
    int d = end - beg;
    float inv = (d > 0) ? 1.0f / (float)d : 0.f;
    g_mean[(size_t)node * IN_DIM + t] = acc * inv;
}

// ---------------- weight prep: transpose + bf16 split (plain [n][k] layout) ----------------
__global__ void prep_b1(const float* __restrict__ Wl, const float* __restrict__ Wr) {
    int e = blockIdx.x * blockDim.x + threadIdx.x;   // 65536
    int n = e & 255, kg = e >> 8;                     // reads coalesced over n
    float v = (kg < 128) ? Wl[kg * HID_DIM + n] : Wr[(kg - 128) * HID_DIM + n];
    __nv_bfloat16 hi = __float2bfloat16(v);
    __nv_bfloat16 lo = __float2bfloat16(v - __bfloat162float(hi));
    g_B1hi[n * 256 + kg] = hi;
    g_B1lo[n * 256 + kg] = lo;
}
__global__ void prep_b2(const float* __restrict__ Wout) {
    int e = blockIdx.x * blockDim.x + threadIdx.x;   // 16384
    int n = e & 63, kg = e >> 6;
    float v = Wout[kg * OUT_DIM + n];
    __nv_bfloat16 hi = __float2bfloat16(v);
    __nv_bfloat16 lo = __float2bfloat16(v - __bfloat162float(hi));
    g_B2hi[n * 256 + kg] = hi;
    g_B2lo[n * 256 + kg] = lo;
}

// ---------------- GEMM1 (HMMA): H = elu([mean|x] @ [W_l;W_r] + b_l) -> bf16 split ----------------
// grid (391, 4): BM=128, BN=64, K=256 in BK=32 chunks. 256 thr = 8 warps (4x2), warp 32x32.
#define LDA 40   // smem row stride in halves (80B: 16B-aligned, ldmatrix conflict-free)

__global__ void __launch_bounds__(256) gemm1_mma(const float* __restrict__ x,
                                                 const float* __restrict__ bl) {
    __shared__ __nv_bfloat16 sA[2][128 * LDA];   // [hi/lo][m][k]
    __shared__ __nv_bfloat16 sB[2][64 * LDA];    // [hi/lo][n][k]
    const int tid = threadIdx.x, lane = tid & 31, wid = tid >> 5;
    const int wr = wid & 3, wc = wid >> 2;
    const int rowBase = blockIdx.x * 128;
    const int colBase = blockIdx.y * 64;
    const uint32_t sA0 = s2u(&sA[0][0]), sA1 = s2u(&sA[1][0]);
    const uint32_t sB0 = s2u(&sB[0][0]), sB1 = s2u(&sB[1][0]);

    float acc[2][4][4];
    #pragma unroll
    for (int i = 0; i < 2; i++)
        #pragma unroll
        for (int j = 0; j < 4; j++)
            #pragma unroll
            for (int q = 0; q < 4; q++) acc[i][j][q] = 0.f;

    const int arow = tid >> 1, aseg = tid & 1;          // A staging: row, 16-col segment
    const int grow = rowBase + arow;
    const bool okrow = grow < NN;
    const int bsplit = tid >> 7, bidx = tid & 127;      // B staging
    const int brow = bidx >> 1, bseg = bidx & 1;

    for (int kc = 0; kc < 8; kc++) {
        // ---- stage A: fp32 -> bf16 split, 16 floats per thread ----
        {
            const float* src = (kc < 4)
                ? g_mean + (size_t)grow * IN_DIM + kc * 32 + aseg * 16
                : x      + (size_t)grow * IN_DIM + (kc - 4) * 32 + aseg * 16;
            float f[16];
            if (okrow) {
                #pragma unroll
                for (int q = 0; q < 4; q++) {
                    float4 v = *(const float4*)(src + q * 4);
                    f[q * 4] = v.x; f[q * 4 + 1] = v.y; f[q * 4 + 2] = v.z; f[q * 4 + 3] = v.w;
                }
            } else {
                #pragma unroll
                for (int q = 0; q < 16; q++) f[q] = 0.f;
            }
            union { __nv_bfloat16 h[16]; uint4 u[2]; } ph, pl;
            #pragma unroll
            for (int q = 0; q < 16; q++) {
                __nv_bfloat16 hi = __float2bfloat16(f[q]);
                ph.h[q] = hi;
                pl.h[q] = __float2bfloat16(f[q] - __bfloat162float(hi));
            }
            __nv_bfloat16* dh = &sA[0][arow * LDA + aseg * 16];
            __nv_bfloat16* dl = &sA[1][arow * LDA + aseg * 16];
            *(uint4*)(dh) = ph.u[0]; *(uint4*)(dh + 8) = ph.u[1];
            *(uint4*)(dl) = pl.u[0]; *(uint4*)(dl + 8) = pl.u[1];
        }
        // ---- stage B: copy split image rows [colBase+brow], cols kc*32+bseg*16 ----
        {
            const __nv_bfloat16* srcp = (bsplit == 0 ? g_B1hi : g_B1lo)
                + (colBase + brow) * 256 + kc * 32 + bseg * 16;
            __nv_bfloat16* dst = &sB[bsplit][brow * LDA + bseg * 16];
            *(uint4*)(dst)     = *(const uint4*)(srcp);
            *(uint4*)(dst + 8) = *(const uint4*)(srcp + 8);
        }
        __syncthreads();

        // ---- compute: 2 k16 steps ----
        #pragma unroll
        for (int ks = 0; ks < 2; ks++) {
            const int kcol = ks * 16;
            uint32_t ah[2][4], al[2][4];
            #pragma unroll
            for (int mi = 0; mi < 2; mi++) {
                int mrow = wr * 32 + mi * 16 + (lane & 15);
                int coff = kcol + ((lane >> 4) << 3);
                uint32_t byteoff = (uint32_t)(mrow * LDA + coff) * 2;
                ldsm4(ah[mi], sA0 + byteoff);
                ldsm4(al[mi], sA1 + byteoff);
            }
            uint32_t bh[2][4], blr[2][4];
            #pragma unroll
            for (int p = 0; p < 2; p++) {
                int nrow = wc * 32 + p * 16 + (lane & 7) + ((lane >> 4) << 3);
                int coff = kcol + (((lane >> 3) & 1) << 3);
                uint32_t byteoff = (uint32_t)(nrow * LDA + coff) * 2;
                ldsm4(bh[p],  sB0 + byteoff);
                ldsm4(blr[p], sB1 + byteoff);
            }
            #pragma unroll
            for (int mi = 0; mi < 2; mi++)
                #pragma unroll
                for (int p = 0; p < 2; p++)
                    #pragma unroll
                    for (int q = 0; q < 2; q++) {
                        float* d = acc[mi][p * 2 + q];
                        mma16816(d, ah[mi], bh[p][q * 2],  bh[p][q * 2 + 1]);
                        mma16816(d, ah[mi], blr[p][q * 2], blr[p][q * 2 + 1]);
                        mma16816(d, al[mi], bh[p][q * 2],  bh[p][q * 2 + 1]);
                    }
        }
        __syncthreads();
    }

    // ---- epilogue: bias + ELU -> bf16 split store ----
    #pragma unroll
    for (int mi = 0; mi < 2; mi++)
        #pragma unroll
        for (int nj = 0; nj < 4; nj++) {
            int r0 = rowBase + wr * 32 + mi * 16 + (lane >> 2);
            int c0 = colBase + wc * 32 + nj * 8 + 2 * (lane & 3);
            float b0 = bl[c0], b1 = bl[c0 + 1];
            #pragma unroll
            for (int half = 0; half < 2; half++) {
                int row = r0 + half * 8;
                if (row >= NN) continue;
                float v0 = acc[mi][nj][half * 2]     + b0;
                float v1 = acc[mi][nj][half * 2 + 1] + b1;
                v0 = (v0 > 0.f) ? v0 : expm1f(v0);
                v1 = (v1 > 0.f) ? v1 : expm1f(v1);
                __nv_bfloat16 h0 = __float2bfloat16(v0);
                __nv_bfloat16 h1 = __float2bfloat16(v1);
                __nv_bfloat16 l0 = __float2bfloat16(v0 - __bfloat162float(h0));
                __nv_bfloat16 l1 = __float2bfloat16(v1 - __bfloat162float(h1));
                *(uint32_t*)(g_hhi + (size_t)row * HID_DIM + c0) = pack2(h0, h1);
                *(uint32_t*)(g_hlo + (size_t)row * HID_DIM + c0) = pack2(l0, l1);
            }
        }
}

// ---------------- GEMM2 (HMMA): out = H @ W_out + b_out ----------------
// grid (391): BM=128, BN=64, K=256. Same skeleton; A is already bf16 split.
__global__ void __launch_bounds__(256) gemm2_mma(const float* __restrict__ bout,
                                                 float* __restrict__ out) {
    __shared__ __nv_bfloat16 sA[2][128 * LDA];
    __shared__ __nv_bfloat16 sB[2][64 * LDA];
    const int tid = threadIdx.x, lane = tid & 31, wid = tid >> 5;
    const int wr = wid & 3, wc = wid >> 2;
    const int rowBase = blockIdx.x * 128;
    const uint32_t sA0 = s2u(&sA[0][0]), sA1 = s2u(&sA[1][0]);
    const uint32_t sB0 = s2u(&sB[0][0]), sB1 = s2u(&sB[1][0]);

    float acc[2][4][4];
    #pragma unroll
    for (int i = 0; i < 2; i++)
        #pragma unroll
        for (int j = 0; j < 4; j++)
            #pragma unroll
            for (int q = 0; q < 4; q++) acc[i][j][q] = 0.f;

    const int arow = tid >> 1, aseg = tid & 1;
    const int grow = rowBase + arow;
    const bool okrow = grow < NN;
    const int bsplit = tid >> 7, bidx = tid & 127;
    const int brow = bidx >> 1, bseg = bidx & 1;
    const uint4 z4 = make_uint4(0, 0, 0, 0);

    for (int kc = 0; kc < 8; kc++) {
        // stage A (copy bf16 split)
        {
            const __nv_bfloat16* shp = g_hhi + (size_t)grow * HID_DIM + kc * 32 + aseg * 16;
            const __nv_bfloat16* slp = g_hlo + (size_t)grow * HID_DIM + kc * 32 + aseg * 16;
            __nv_bfloat16* dh = &sA[0][arow * LDA + aseg * 16];
            __nv_bfloat16* dl = &sA[1][arow * LDA + aseg * 16];
            *(uint4*)(dh)     = okrow ? *(const uint4*)(shp)     : z4;
            *(uint4*)(dh + 8) = okrow ? *(const uint4*)(shp + 8) : z4;
            *(uint4*)(dl)     = okrow ? *(const uint4*)(slp)     : z4;
            *(uint4*)(dl + 8) = okrow ? *(const uint4*)(slp + 8) : z4;
        }
        // stage B
        {
            const __nv_bfloat16* srcp = (bsplit == 0 ? g_B2hi : g_B2lo)
                + brow * 256 + kc * 32 + bseg * 16;
            __nv_bfloat16* dst = &sB[bsplit][brow * LDA + bseg * 16];
            *(uint4*)(dst)     = *(const uint4*)(srcp);
            *(uint4*)(dst + 8) = *(const uint4*)(srcp + 8);
        }
        __syncthreads();

        #pragma unroll
        for (int ks = 0; ks < 2; ks++) {
            const int kcol = ks * 16;
            uint32_t ah[2][4], al[2][4];
            #pragma unroll
            for (int mi = 0; mi < 2; mi++) {
                int mrow = wr * 32 + mi * 16 + (lane & 15);
                int coff = kcol + ((lane >> 4) << 3);
                uint32_t byteoff = (uint32_t)(mrow * LDA + coff) * 2;
                ldsm4(ah[mi], sA0 + byteoff);
                ldsm4(al[mi], sA1 + byteoff);
            }
            uint32_t bh[2][4], blr[2][4];
            #pragma unroll
            for (int p = 0; p < 2; p++) {
                int nrow = wc * 32 + p * 16 + (lane & 7) + ((lane >> 4) << 3);
                int coff = kcol + (((lane >> 3) & 1) << 3);
                uint32_t byteoff = (uint32_t)(nrow * LDA + coff) * 2;
                ldsm4(bh[p],  sB0 + byteoff);
                ldsm4(blr[p], sB1 + byteoff);
            }
            #pragma unroll
            for (int mi = 0; mi < 2; mi++)
                #pragma unroll
                for (int p = 0; p < 2; p++)
                    #pragma unroll
                    for (int q = 0; q < 2; q++) {
                        float* d = acc[mi][p * 2 + q];
                        mma16816(d, ah[mi], bh[p][q * 2],  bh[p][q * 2 + 1]);
                        mma16816(d, ah[mi], blr[p][q * 2], blr[p][q * 2 + 1]);
                        mma16816(d, al[mi], bh[p][q * 2],  bh[p][q * 2 + 1]);
                    }
        }
        __syncthreads();
    }

    // epilogue: + bias, fp32 float2 stores
    #pragma unroll
    for (int mi = 0; mi < 2; mi++)
        #pragma unroll
        for (int nj = 0; nj < 4; nj++) {
            int r0 = rowBase + wr * 32 + mi * 16 + (lane >> 2);
            int c0 = wc * 32 + nj * 8 + 2 * (lane & 3);
            float b0 = bout[c0], b1 = bout[c0 + 1];
            #pragma unroll
            for (int half = 0; half < 2; half++) {
                int row = r0 + half * 8;
                if (row >= NN) continue;
                float2 v = make_float2(acc[mi][nj][half * 2] + b0,
                                       acc[mi][nj][half * 2 + 1] + b1);
                *(float2*)(out + (size_t)row * OUT_DIM + c0) = v;
            }
        }
}

// ---------------- launch ----------------
extern "C" void kernel_launch(void* const* d_in, const int* in_sizes, int n_in,
                              void* d_out, int out_size) {
    const float* x    = (const float*)d_in[0];
    const void*  ei   = d_in[1];
    const float* Wl   = (const float*)d_in[2];
    const float* bl   = (const float*)d_in[3];
    const float* Wr   = (const float*)d_in[4];
    const float* Wout = (const float*)d_in[5];
    const float* bout = (const float*)d_in[6];
    float* out = (float*)d_out;

    detect_kernel<<<1, 256>>>((const unsigned int*)ei);
    zero_deg_kernel<<<(NN + 255) / 256, 256>>>();
    convert_kernel<<<(NE + 255) / 256, 256>>>(ei);
    scan1_kernel<<<SCAN_BLOCKS, 1024>>>();
    scan2_kernel<<<1, 32>>>();
    scan3_kernel<<<SCAN_BLOCKS, 1024>>>();
    scatter_kernel<<<(NE + 255) / 256, 256>>>();
    prep_b1<<<256, 256>>>(Wl, Wr);
    prep_b2<<<64, 256>>>(Wout);
    agg_kernel<<<NN, 128>>>(x);

    dim3 g1(MTILES, 4);
    gemm1_mma<<<g1, 256>>>(x, bl);
    gemm2_mma<<<MTILES, 256>>>(bout, out);
}